// round 6
// baseline (speedup 1.0000x reference)
#include <cuda_runtime.h>
#include <cuda_bf16.h>
#include <cstdint>

#define BSZ 512
#define NN  128
#define HX  256
#define HL  64
#define HY  128
#define ROWS (BSZ*NN)          // 65536
#define KXL 320
#define KH  448

typedef __nv_bfloat16 bf16;

// ---------------- scratch (bf16 hi/lo planes) ----------------
__device__ float    g_dinv[ROWS];
__device__ unsigned g_mask[(size_t)ROWS*4];
__device__ bf16     g_Thi[(size_t)ROWS*KXL];
__device__ bf16     g_Tlo[(size_t)ROWS*KXL];
__device__ bf16     g_Hhi[(size_t)ROWS*KXL];
__device__ bf16     g_Hlo[(size_t)ROWS*KXL];
__device__ bf16     g_Wxh[320*256], g_Wxl[320*256];
__device__ bf16     g_W1h[448*256], g_W1l[448*256];

// ---------------- helpers ----------------
__device__ __forceinline__ uint32_t smem_u32(const void* p) {
    uint32_t a;
    asm("{ .reg .u64 t; cvta.to.shared.u64 t, %1; cvt.u32.u64 %0, t; }" : "=r"(a) : "l"(p));
    return a;
}
__device__ __forceinline__ float warp_sum(float v) {
#pragma unroll
    for (int o = 16; o; o >>= 1) v += __shfl_xor_sync(0xffffffffu, v, o);
    return v;
}
__device__ __forceinline__ void split2(float a, float b, uint32_t& hi, uint32_t& lo) {
    __nv_bfloat162 h = __floats2bfloat162_rn(a, b);
    float ra = a - __bfloat162float(h.x);
    float rb = b - __bfloat162float(h.y);
    __nv_bfloat162 l = __floats2bfloat162_rn(ra, rb);
    hi = *(uint32_t*)&h;
    lo = *(uint32_t*)&l;
}

#define LDSM_X4(R0,R1,R2,R3,ADDR) \
    asm volatile("ldmatrix.sync.aligned.m8n8.x4.shared.b16 {%0,%1,%2,%3}, [%4];" \
        : "=r"(R0), "=r"(R1), "=r"(R2), "=r"(R3) : "r"(ADDR))
#define LDSM_X4T(R0,R1,R2,R3,ADDR) \
    asm volatile("ldmatrix.sync.aligned.m8n8.x4.trans.shared.b16 {%0,%1,%2,%3}, [%4];" \
        : "=r"(R0), "=r"(R1), "=r"(R2), "=r"(R3) : "r"(ADDR))

__device__ __forceinline__ void mma16816(float* c, const uint32_t* a, uint32_t b0, uint32_t b1) {
    asm volatile("mma.sync.aligned.m16n8k16.row.col.f32.bf16.bf16.f32 "
        "{%0,%1,%2,%3}, {%4,%5,%6,%7}, {%8,%9}, {%0,%1,%2,%3};"
        : "+f"(c[0]), "+f"(c[1]), "+f"(c[2]), "+f"(c[3])
        : "r"(a[0]), "r"(a[1]), "r"(a[2]), "r"(a[3]), "r"(b0), "r"(b1));
}

// ---------------- prep: degree + adjacency bitmask ----------------
__global__ void dinv_mask_kernel(const int* __restrict__ E, float* __restrict__ dinv,
                                 unsigned* __restrict__ mask) {
    int t = threadIdx.x, w = t >> 5, l = t & 31;
    size_t row = (size_t)blockIdx.x * 8 + w;
    const int* er = E + row * 256 + 1;
    int cnt = 0;
#pragma unroll
    for (int c = 0; c < 4; c++) {
        unsigned b = __ballot_sync(0xffffffffu, er[(size_t)(c * 32 + l) * 2] != 0);
        if (l == 0) mask[row * 4 + c] = b;
        cnt += __popc(b);
    }
    if (l == 0) dinv[row] = rsqrtf((float)cnt + 1.0f);
}

// ---------------- prep: split weights into bf16 planes ----------------
__global__ void wsplit_kernel(const float* __restrict__ W, int total,
                              bf16* __restrict__ oh, bf16* __restrict__ ol) {
    int idx = blockIdx.x * 256 + threadIdx.x;
    if (idx >= total) return;
    float v = W[idx];
    bf16 h = __float2bfloat16(v);
    oh[idx] = h;
    ol[idx] = __float2bfloat16(v - __bfloat162float(h));
}

// ---------------- big MMA GEMM: 128x256 block, 512 threads ----------------
// MODE 0: T(split planes) = dinv * ([X|label] @ Wx)   (K=320)
// MODE 1: out_X = LN(relu([H|y]@W1+b1))               (K=448)
template<int MODE>
__global__ void __launch_bounds__(512, 1) gemm_mma(
    const float* __restrict__ A0, const float* __restrict__ A1,
    const bf16* __restrict__ Ah, const bf16* __restrict__ Al,
    const bf16* __restrict__ Bh, const bf16* __restrict__ Bl,
    const float* __restrict__ bias, const float* __restrict__ gam,
    const float* __restrict__ bet, const float* __restrict__ dinv,
    float* __restrict__ C, bf16* __restrict__ Ch, bf16* __restrict__ Cl)
{
    extern __shared__ char sm[];
    constexpr int K  = MODE ? KH : KXL;
    constexpr int NC = K / 16;

    bf16* AsH = (bf16*)(sm);
    bf16* AsL = (bf16*)(sm + 12288);
    bf16* BsH = (bf16*)(sm + 24576);
    bf16* BsL = (bf16*)(sm + 41472);
    float* bias_s = (float*)(sm + 58368);
    float* gam_s  = (float*)(sm + 59392);
    float* bet_s  = (float*)(sm + 60416);
    float* rsum   = (float*)(sm + 61440);
    float* rsq    = (float*)(sm + 63488);
    float* mstd   = (float*)(sm + 65536);
    float* dinv_s = (float*)(sm + 61440);   // MODE0 alias

    const int t = threadIdx.x, lane = t & 31, wid = t >> 5;
    const int wm = wid >> 2, wn = wid & 3;
    const size_t brow = (size_t)blockIdx.x * 128;
    const int bidx = blockIdx.x;

    if (MODE == 1 && t < 256) { bias_s[t] = bias[t]; gam_s[t] = gam[t]; bet_s[t] = bet[t]; }
    if (MODE == 0 && t < 128) dinv_s[t] = dinv[brow + t];

    const uint32_t aRow = wm * 32 + (lane & 15);
    const uint32_t aOffH = smem_u32(AsH) + (aRow * 24 + (lane >> 4) * 8) * 2;
    const uint32_t aOffL = aOffH + 12288;
    const uint32_t bCol = wn * 64 + ((lane >> 4) << 3);
    const uint32_t bOffH = smem_u32(BsH) + ((lane & 15) * 264 + bCol) * 2;
    const uint32_t bOffL = bOffH + 16896;

    float acc[2][8][4] = {};
    uint2 pah, pal;
    uint4 pbh, pbl;
    const int arL = t >> 2, ac4 = t & 3;
    const int bk = t >> 5, bn8 = t & 31;

#define LOADG(k0) do {                                                        \
        int col = (k0) + ac4 * 4;                                             \
        if (MODE == 0) {                                                      \
            float4 v = (col < 256)                                            \
                ? *(const float4*)(A0 + (brow + arL) * 256 + col)             \
                : *(const float4*)(A1 + (brow + arL) * 64 + (col - 256));     \
            split2(v.x, v.y, pah.x, pal.x); split2(v.z, v.w, pah.y, pal.y);   \
        } else {                                                              \
            if (col < 320) {                                                  \
                pah = *(const uint2*)(Ah + (brow + arL) * (size_t)KXL + col); \
                pal = *(const uint2*)(Al + (brow + arL) * (size_t)KXL + col); \
            } else {                                                          \
                float4 v = *(const float4*)(A1 + (size_t)bidx * 128 + (col - 320)); \
                split2(v.x, v.y, pah.x, pal.x); split2(v.z, v.w, pah.y, pal.y); \
            }                                                                 \
        }                                                                     \
        pbh = *(const uint4*)(Bh + (size_t)((k0) + bk) * 256 + bn8 * 8);      \
        pbl = *(const uint4*)(Bl + (size_t)((k0) + bk) * 256 + bn8 * 8);      \
    } while (0)

#define STORES(buf) do {                                                      \
        *(uint2*)(AsH + (buf) * 3072 + arL * 24 + ac4 * 4) = pah;             \
        *(uint2*)(AsL + (buf) * 3072 + arL * 24 + ac4 * 4) = pal;             \
        *(uint4*)(BsH + (buf) * 4224 + bk * 264 + bn8 * 8) = pbh;             \
        *(uint4*)(BsL + (buf) * 4224 + bk * 264 + bn8 * 8) = pbl;             \
    } while (0)

    LOADG(0);
    int buf = 0;
#pragma unroll 1
    for (int c = 0; c < NC; c++) {
        STORES(buf);
        if (c + 1 < NC) LOADG((c + 1) * 16);
        __syncthreads();
        uint32_t ah[2][4], al[2][4];
#pragma unroll
        for (int mt = 0; mt < 2; mt++) {
            LDSM_X4(ah[mt][0], ah[mt][1], ah[mt][2], ah[mt][3], aOffH + buf * 6144 + mt * 768);
            LDSM_X4(al[mt][0], al[mt][1], al[mt][2], al[mt][3], aOffL + buf * 6144 + mt * 768);
        }
#pragma unroll
        for (int np = 0; np < 4; np++) {
            uint32_t bh[4], bl[4];
            LDSM_X4T(bh[0], bh[1], bh[2], bh[3], bOffH + buf * 8448 + np * 32);
            LDSM_X4T(bl[0], bl[1], bl[2], bl[3], bOffL + buf * 8448 + np * 32);
#pragma unroll
            for (int mt = 0; mt < 2; mt++) {
                mma16816(acc[mt][np * 2],     ah[mt], bh[0], bh[1]);
                mma16816(acc[mt][np * 2 + 1], ah[mt], bh[2], bh[3]);
                mma16816(acc[mt][np * 2],     ah[mt], bl[0], bl[1]);
                mma16816(acc[mt][np * 2 + 1], ah[mt], bl[2], bl[3]);
                mma16816(acc[mt][np * 2],     al[mt], bh[0], bh[1]);
                mma16816(acc[mt][np * 2 + 1], al[mt], bh[2], bh[3]);
            }
        }
        buf ^= 1;
    }

    const int g = lane >> 2, q = (lane & 3) * 2;
    if (MODE == 0) {
#pragma unroll
        for (int mt = 0; mt < 2; mt++) {
            int r0loc = wm * 32 + mt * 16 + g;
            float d0 = dinv_s[r0loc], d1 = dinv_s[r0loc + 8];
#pragma unroll
            for (int nt = 0; nt < 8; nt++) {
                const float* a = acc[mt][nt];
                int col = wn * 64 + nt * 8 + q;
                size_t r0 = brow + r0loc;
                uint32_t h, l;
                split2(a[0] * d0, a[1] * d0, h, l);
                *(uint32_t*)(Ch + r0 * KXL + col) = h;
                *(uint32_t*)(Cl + r0 * KXL + col) = l;
                split2(a[2] * d1, a[3] * d1, h, l);
                *(uint32_t*)(Ch + (r0 + 8) * KXL + col) = h;
                *(uint32_t*)(Cl + (r0 + 8) * KXL + col) = l;
            }
        }
    } else {
#pragma unroll
        for (int mt = 0; mt < 2; mt++) {
#pragma unroll
            for (int hf = 0; hf < 2; hf++) {
                float s = 0.f, qq = 0.f;
#pragma unroll
                for (int nt = 0; nt < 8; nt++) {
                    int col = wn * 64 + nt * 8 + q;
                    float v0 = fmaxf(acc[mt][nt][hf * 2]     + bias_s[col],     0.f);
                    float v1 = fmaxf(acc[mt][nt][hf * 2 + 1] + bias_s[col + 1], 0.f);
                    s += v0 + v1; qq += v0 * v0 + v1 * v1;
                }
                s  += __shfl_xor_sync(0xffffffffu, s, 1);
                s  += __shfl_xor_sync(0xffffffffu, s, 2);
                qq += __shfl_xor_sync(0xffffffffu, qq, 1);
                qq += __shfl_xor_sync(0xffffffffu, qq, 2);
                if ((lane & 3) == 0) {
                    int row = wm * 32 + mt * 16 + hf * 8 + g;
                    rsum[row * 4 + wn] = s;
                    rsq [row * 4 + wn] = qq;
                }
            }
        }
        __syncthreads();
        if (t < 128) {
            float S  = rsum[t * 4] + rsum[t * 4 + 1] + rsum[t * 4 + 2] + rsum[t * 4 + 3];
            float Q  = rsq [t * 4] + rsq [t * 4 + 1] + rsq [t * 4 + 2] + rsq [t * 4 + 3];
            float mean = S * (1.0f / 256.0f);
            float var  = Q * (1.0f / 256.0f) - mean * mean;
            mstd[t * 2]     = mean;
            mstd[t * 2 + 1] = rsqrtf(var + 1e-5f);
        }
        __syncthreads();
#pragma unroll
        for (int mt = 0; mt < 2; mt++)
#pragma unroll
            for (int nt = 0; nt < 8; nt++) {
                const float* a = acc[mt][nt];
                int col = wn * 64 + nt * 8 + q;
                float b0 = bias_s[col], b1 = bias_s[col + 1];
                float g0 = gam_s[col],  g1 = gam_s[col + 1];
                float e0 = bet_s[col],  e1 = bet_s[col + 1];
                int r0 = wm * 32 + mt * 16 + g;
                float m0 = mstd[r0 * 2], s0 = mstd[r0 * 2 + 1];
                float m1 = mstd[(r0 + 8) * 2], s1 = mstd[(r0 + 8) * 2 + 1];
                float v0 = fmaxf(a[0] + b0, 0.f), v1 = fmaxf(a[1] + b1, 0.f);
                float v2 = fmaxf(a[2] + b0, 0.f), v3 = fmaxf(a[3] + b1, 0.f);
                *(float2*)&C[(brow + r0) * (size_t)HX + col] =
                    make_float2((v0 - m0) * s0 * g0 + e0, (v1 - m0) * s0 * g1 + e1);
                *(float2*)&C[(brow + r0 + 8) * (size_t)HX + col] =
                    make_float2((v2 - m1) * s1 * g0 + e0, (v3 - m1) * s1 * g1 + e1);
            }
    }
#undef LOADG
#undef STORES
}

// ---------------- batched (A+I) MMA GEMM, 128x80 block, 256 threads ----------------
__global__ void __launch_bounds__(256, 4) an_mma(
    const unsigned* __restrict__ mask, const float* __restrict__ dinv,
    const bf16* __restrict__ Thi, const bf16* __restrict__ Tlo,
    const float* __restrict__ bx, const float* __restrict__ bl,
    bf16* __restrict__ Hhi, bf16* __restrict__ Hlo)
{
    __shared__ bf16 As[128 * 136];
    __shared__ bf16 BsH[2][16 * 88];
    __shared__ bf16 BsL[2][16 * 88];
    __shared__ float bias_s[80];
    __shared__ float dinv_s[128];

    const int t = threadIdx.x, lane = t & 31, wid = t >> 5;   // 8 warps
    const int ct = blockIdx.x, b = blockIdx.y;
    const bf16* Tbh = Thi + (size_t)b * 128 * KXL + ct * 80;
    const bf16* Tbl = Tlo + (size_t)b * 128 * KXL + ct * 80;

    // generate A01 = adj + I (exact bf16 {0,1,2})
#pragma unroll
    for (int j = 0; j < 2; j++) {
        int idx = t + j * 256;
        int i = idx >> 2, jg = idx & 3;
        unsigned m = mask[((size_t)b * 128 + i) * 4 + jg];
        uint32_t* dst = (uint32_t*)(As + i * 136 + jg * 32);
#pragma unroll
        for (int p = 0; p < 16; p++) {
            int j0 = jg * 32 + p * 2;
            uint32_t s0 = ((m >> (p * 2)) & 1u) + (j0 == i);
            uint32_t s1 = ((m >> (p * 2 + 1)) & 1u) + (j0 + 1 == i);
            uint32_t v0 = (s0 == 0) ? 0u : ((s0 == 1) ? 0x3F80u : 0x4000u);
            uint32_t v1 = (s1 == 0) ? 0u : ((s1 == 1) ? 0x3F80u : 0x4000u);
            dst[p] = v0 | (v1 << 16);
        }
    }
    if (t < 80) {
        int gcol = ct * 80 + t;
        bias_s[t] = (gcol < 256) ? bx[gcol] : bl[gcol - 256];
    }
    if (t >= 128 && t < 256) dinv_s[t - 128] = dinv[(size_t)b * 128 + (t - 128)];

    const uint32_t aOff = smem_u32(As) + ((wid * 16 + (lane & 15)) * 136 + (lane >> 4) * 8) * 2;
    const uint32_t bOffH = smem_u32(BsH) + ((lane & 15) * 88 + ((lane >> 4) << 3)) * 2;
    const uint32_t bOffL = smem_u32(BsL) + ((lane & 15) * 88 + ((lane >> 4) << 3)) * 2;

    float acc[10][4] = {};
    uint2 pb[3];

#define BLOAD(k0) do {                                                        \
        _Pragma("unroll")                                                     \
        for (int j = 0; j < 3; j++) {                                         \
            int idx = t + j * 256;                                            \
            if (idx < 640) {                                                  \
                int pl = idx >= 320;                                          \
                int p = idx - pl * 320;                                       \
                int k = p / 20, n4 = p % 20;                                  \
                const bf16* src = pl ? Tbl : Tbh;                             \
                pb[j] = *(const uint2*)(src + (size_t)((k0) + k) * KXL + n4 * 4); \
            }                                                                 \
        }                                                                     \
    } while (0)

#define BSTORE(buf) do {                                                      \
        _Pragma("unroll")                                                     \
        for (int j = 0; j < 3; j++) {                                         \
            int idx = t + j * 256;                                            \
            if (idx < 640) {                                                  \
                int pl = idx >= 320;                                          \
                int p = idx - pl * 320;                                       \
                int k = p / 20, n4 = p % 20;                                  \
                bf16* dst = pl ? &BsL[buf][0] : &BsH[buf][0];                 \
                *(uint2*)(dst + k * 88 + n4 * 4) = pb[j];                     \
            }                                                                 \
        }                                                                     \
    } while (0)

    BLOAD(0);
    int buf = 0;
#pragma unroll 1
    for (int c = 0; c < 8; c++) {
        BSTORE(buf);
        if (c + 1 < 8) BLOAD((c + 1) * 16);
        __syncthreads();
        uint32_t a[4];
        LDSM_X4(a[0], a[1], a[2], a[3], aOff + c * 32);
#pragma unroll
        for (int nt = 0; nt < 5; nt++) {
            uint32_t bh[4], blr[4];
            LDSM_X4T(bh[0], bh[1], bh[2], bh[3], bOffH + buf * 2816 + nt * 32);
            LDSM_X4T(blr[0], blr[1], blr[2], blr[3], bOffL + buf * 2816 + nt * 32);
            mma16816(acc[nt * 2],     a, bh[0], bh[1]);
            mma16816(acc[nt * 2 + 1], a, bh[2], bh[3]);
            mma16816(acc[nt * 2],     a, blr[0], blr[1]);
            mma16816(acc[nt * 2 + 1], a, blr[2], blr[3]);
        }
        buf ^= 1;
    }

    const int g = lane >> 2, q = (lane & 3) * 2;
    const int r0loc = wid * 16 + g;
    const float d0 = dinv_s[r0loc], d1 = dinv_s[r0loc + 8];
#pragma unroll
    for (int nt = 0; nt < 10; nt++) {
        const float* a = acc[nt];
        int lcol = nt * 8 + q;
        int gcol = ct * 80 + lcol;
        float b0 = bias_s[lcol], b1 = bias_s[lcol + 1];
        size_t r0 = (size_t)b * 128 + r0loc;
        uint32_t h, l;
        split2(fmaf(a[0], d0, b0), fmaf(a[1], d0, b1), h, l);
        *(uint32_t*)(Hhi + r0 * KXL + gcol) = h;
        *(uint32_t*)(Hlo + r0 * KXL + gcol) = l;
        split2(fmaf(a[2], d1, b0), fmaf(a[3], d1, b1), h, l);
        *(uint32_t*)(Hhi + (r0 + 8) * KXL + gcol) = h;
        *(uint32_t*)(Hlo + (r0 + 8) * KXL + gcol) = l;
    }
#undef BLOAD
#undef BSTORE
}

// ---------------- 64x64x64 SGEMM (label@Wl, dinv-scaled, split-store) ----------------
__global__ void sgemm64(const float* __restrict__ A, const float* __restrict__ B,
                        const float* __restrict__ dinv,
                        bf16* __restrict__ Ch, bf16* __restrict__ Cl) {
    __shared__ float As[16][64];
    __shared__ float Bs[16][64];
    const int t = threadIdx.x;
    const size_t brow = (size_t)blockIdx.y * 64;
    const int tx = t & 15, ty = t >> 4;
    const int ar = t >> 2, ac = (t & 3) * 4;
    const int bkr = t >> 4, bc = (t & 15) * 4;
    float acc[4][4] = {};
    for (int k0 = 0; k0 < 64; k0 += 16) {
        float4 av = *(const float4*)(A + (brow + ar) * 64 + k0 + ac);
        As[ac + 0][ar] = av.x; As[ac + 1][ar] = av.y;
        As[ac + 2][ar] = av.z; As[ac + 3][ar] = av.w;
        *(float4*)&Bs[bkr][bc] = *(const float4*)(B + (size_t)(k0 + bkr) * 64 + bc);
        __syncthreads();
#pragma unroll
        for (int kk = 0; kk < 16; kk++) {
            float4 a0 = *(const float4*)&As[kk][ty * 4];
            float4 b0 = *(const float4*)&Bs[kk][tx * 4];
            float ra[4] = {a0.x, a0.y, a0.z, a0.w};
            float rb[4] = {b0.x, b0.y, b0.z, b0.w};
#pragma unroll
            for (int i = 0; i < 4; i++)
#pragma unroll
                for (int j = 0; j < 4; j++)
                    acc[i][j] = fmaf(ra[i], rb[j], acc[i][j]);
        }
        __syncthreads();
    }
#pragma unroll
    for (int i = 0; i < 4; i++) {
        size_t row = brow + ty * 4 + i;
        float d = dinv[row];
        uint32_t h0, l0, h1, l1;
        split2(acc[i][0] * d, acc[i][1] * d, h0, l0);
        split2(acc[i][2] * d, acc[i][3] * d, h1, l1);
        size_t off = row * KXL + 256 + tx * 4;
        *(uint2*)(Ch + off) = make_uint2(h0, h1);
        *(uint2*)(Cl + off) = make_uint2(l0, l1);
    }
}

// ---------------- fused relu(la@W2+b2) + LN(64) ----------------
__global__ void label_out_kernel(const bf16* __restrict__ Hhi, const bf16* __restrict__ Hlo,
                                 const float* __restrict__ W2,
                                 const float* __restrict__ b2, const float* __restrict__ g2,
                                 const float* __restrict__ be2, float* __restrict__ out) {
    __shared__ float W2s[64][64];
    __shared__ float las[8][64];
    const int t = threadIdx.x, w = t >> 5, l = t & 31;
#pragma unroll
    for (int i = 0; i < 4; i++) {
        int idx = t + i * 256;
        ((float4*)&W2s[0][0])[idx] = ((const float4*)W2)[idx];
    }
    size_t row = (size_t)blockIdx.x * 8 + w;
    size_t base = row * KXL + HX;
    las[w][l]      = __bfloat162float(Hhi[base + l])      + __bfloat162float(Hlo[base + l]);
    las[w][l + 32] = __bfloat162float(Hhi[base + l + 32]) + __bfloat162float(Hlo[base + l + 32]);
    __syncthreads();
    float acc0 = 0.f, acc1 = 0.f;
#pragma unroll
    for (int k = 0; k < 64; k++) {
        float v = las[w][k];
        acc0 = fmaf(v, W2s[k][l], acc0);
        acc1 = fmaf(v, W2s[k][l + 32], acc1);
    }
    acc0 = fmaxf(acc0 + b2[l], 0.f);
    acc1 = fmaxf(acc1 + b2[l + 32], 0.f);
    float mean = warp_sum(acc0 + acc1) * (1.0f / 64.0f);
    float sq = warp_sum(acc0 * acc0 + acc1 * acc1) * (1.0f / 64.0f);
    float r = rsqrtf(sq - mean * mean + 1e-5f);
    out[row * HL + l]      = (acc0 - mean) * r * g2[l] + be2[l];
    out[row * HL + l + 32] = (acc1 - mean) * r * g2[l + 32] + be2[l + 32];
}

// ---------------- launcher ----------------
extern "C" void kernel_launch(void* const* d_in, const int* in_sizes, int n_in,
                              void* d_out, int out_size) {
    const float* X     = (const float*)d_in[0];
    const int*   E     = (const int*)d_in[1];
    const float* y     = (const float*)d_in[2];
    const float* label = (const float*)d_in[3];
    const float* Wx  = (const float*)d_in[5];
    const float* bx  = (const float*)d_in[6];
    const float* Wl  = (const float*)d_in[7];
    const float* bl  = (const float*)d_in[8];
    const float* W1  = (const float*)d_in[9];
    const float* b1  = (const float*)d_in[10];
    const float* g1  = (const float*)d_in[11];
    const float* be1 = (const float*)d_in[12];
    const float* W2  = (const float*)d_in[13];
    const float* b2  = (const float*)d_in[14];
    const float* g2  = (const float*)d_in[15];
    const float* be2 = (const float*)d_in[16];
    float* out_X = (float*)d_out;
    float* out_L = out_X + (size_t)ROWS * HX;

    float* pdinv;
    unsigned* pmask;
    bf16 *pThi, *pTlo, *pHhi, *pHlo, *pWxh, *pWxl, *pW1h, *pW1l;
    cudaGetSymbolAddress((void**)&pdinv, g_dinv);
    cudaGetSymbolAddress((void**)&pmask, g_mask);
    cudaGetSymbolAddress((void**)&pThi,  g_Thi);
    cudaGetSymbolAddress((void**)&pTlo,  g_Tlo);
    cudaGetSymbolAddress((void**)&pHhi,  g_Hhi);
    cudaGetSymbolAddress((void**)&pHlo,  g_Hlo);
    cudaGetSymbolAddress((void**)&pWxh,  g_Wxh);
    cudaGetSymbolAddress((void**)&pWxl,  g_Wxl);
    cudaGetSymbolAddress((void**)&pW1h,  g_W1h);
    cudaGetSymbolAddress((void**)&pW1l,  g_W1l);

    const int SMEM = 66560;
    cudaFuncSetAttribute(gemm_mma<0>, cudaFuncAttributeMaxDynamicSharedMemorySize, SMEM);
    cudaFuncSetAttribute(gemm_mma<1>, cudaFuncAttributeMaxDynamicSharedMemorySize, SMEM);
    cudaFuncSetAttribute(an_mma, cudaFuncAttributePreferredSharedMemoryCarveout, 100);

    dinv_mask_kernel<<<ROWS / 8, 256>>>(E, pdinv, pmask);
    wsplit_kernel<<<(320 * 256 + 255) / 256, 256>>>(Wx, 320 * 256, pWxh, pWxl);
    wsplit_kernel<<<(448 * 256 + 255) / 256, 256>>>(W1, 448 * 256, pW1h, pW1l);

    gemm_mma<0><<<512, 512, SMEM>>>(X, label, nullptr, nullptr, pWxh, pWxl,
                                    nullptr, nullptr, nullptr, pdinv,
                                    nullptr, pThi, pTlo);
    sgemm64<<<dim3(1, ROWS / 64), 256>>>(label, Wl, pdinv, pThi, pTlo);

    an_mma<<<dim3(4, BSZ), 256>>>(pmask, pdinv, pThi, pTlo, bx, bl, pHhi, pHlo);

    gemm_mma<1><<<512, 512, SMEM>>>(nullptr, y, pHhi, pHlo, pW1h, pW1l,
                                    b1, g1, be1, nullptr,
                                    out_X, nullptr, nullptr);

    label_out_kernel<<<ROWS / 8, 256>>>(pHhi, pHlo, W2, b2, g2, be2, out_L);
}

// round 7
// speedup vs baseline: 1.0873x; 1.0873x over previous
#include <cuda_runtime.h>
#include <cuda_bf16.h>
#include <cstdint>

#define BSZ 512
#define NN  128
#define HX  256
#define HL  64
#define HY  128
#define ROWS (BSZ*NN)          // 65536
#define KXL 320
#define KH  448

typedef __nv_bfloat16 bf16;

// ---------------- scratch ----------------
__device__ float    g_dinv[ROWS];
__device__ unsigned g_mask[(size_t)ROWS*4];
__device__ float    g_T [(size_t)ROWS*KXL];     // 84 MB (dinv-scaled T)
__device__ float    g_H [(size_t)ROWS*KXL];     // 84 MB
__device__ float    g_Z [(size_t)ROWS*HX];      // 67 MB relu(h@W1+b1)
__device__ bf16     g_Wxh[320*256], g_Wxl[320*256];
__device__ bf16     g_W1h[448*256], g_W1l[448*256];

// ---------------- helpers ----------------
__device__ __forceinline__ uint32_t smem_u32(const void* p) {
    uint32_t a;
    asm("{ .reg .u64 t; cvta.to.shared.u64 t, %1; cvt.u32.u64 %0, t; }" : "=r"(a) : "l"(p));
    return a;
}
__device__ __forceinline__ float warp_sum(float v) {
#pragma unroll
    for (int o = 16; o; o >>= 1) v += __shfl_xor_sync(0xffffffffu, v, o);
    return v;
}
__device__ __forceinline__ void split2(float a, float b, uint32_t& hi, uint32_t& lo) {
    __nv_bfloat162 h = __floats2bfloat162_rn(a, b);
    float ra = a - __bfloat162float(h.x);
    float rb = b - __bfloat162float(h.y);
    __nv_bfloat162 l = __floats2bfloat162_rn(ra, rb);
    hi = *(uint32_t*)&h;
    lo = *(uint32_t*)&l;
}

#define LDSM_X4(R0,R1,R2,R3,ADDR) \
    asm volatile("ldmatrix.sync.aligned.m8n8.x4.shared.b16 {%0,%1,%2,%3}, [%4];" \
        : "=r"(R0), "=r"(R1), "=r"(R2), "=r"(R3) : "r"(ADDR))
#define LDSM_X4T(R0,R1,R2,R3,ADDR) \
    asm volatile("ldmatrix.sync.aligned.m8n8.x4.trans.shared.b16 {%0,%1,%2,%3}, [%4];" \
        : "=r"(R0), "=r"(R1), "=r"(R2), "=r"(R3) : "r"(ADDR))

__device__ __forceinline__ void mma16816(float* c, const uint32_t* a, uint32_t b0, uint32_t b1) {
    asm volatile("mma.sync.aligned.m16n8k16.row.col.f32.bf16.bf16.f32 "
        "{%0,%1,%2,%3}, {%4,%5,%6,%7}, {%8,%9}, {%0,%1,%2,%3};"
        : "+f"(c[0]), "+f"(c[1]), "+f"(c[2]), "+f"(c[3])
        : "r"(a[0]), "r"(a[1]), "r"(a[2]), "r"(a[3]), "r"(b0), "r"(b1));
}

// ---------------- prep: degree + adjacency bitmask ----------------
__global__ void dinv_mask_kernel(const int* __restrict__ E, float* __restrict__ dinv,
                                 unsigned* __restrict__ mask) {
    int t = threadIdx.x, w = t >> 5, l = t & 31;
    size_t row = (size_t)blockIdx.x * 8 + w;
    const int* er = E + row * 256 + 1;
    int cnt = 0;
#pragma unroll
    for (int c = 0; c < 4; c++) {
        unsigned b = __ballot_sync(0xffffffffu, er[(size_t)(c * 32 + l) * 2] != 0);
        if (l == 0) mask[row * 4 + c] = b;
        cnt += __popc(b);
    }
    if (l == 0) dinv[row] = rsqrtf((float)cnt + 1.0f);
}

// ---------------- prep: split weights into bf16 planes ----------------
__global__ void wsplit_kernel(const float* __restrict__ W, int total,
                              bf16* __restrict__ oh, bf16* __restrict__ ol) {
    int idx = blockIdx.x * 256 + threadIdx.x;
    if (idx >= total) return;
    float v = W[idx];
    bf16 h = __float2bfloat16(v);
    oh[idx] = h;
    ol[idx] = __float2bfloat16(v - __bfloat162float(h));
}

// ---------------- big MMA GEMM: 128x128 block, 256 threads, 2 CTAs/SM ----------------
// MODE 0: T[:, bcol:bcol+128] = dinv * ([X|label] @ Wx)  (K=320, ldc 320)
// MODE 1: Z[:, bcol:bcol+128] = relu([H|y]@W1 + b1)      (K=448, ldc 256)
// smem bytes: AsH 0..12288 (2 bufs x 128x24), AsL 12288..24576,
//             BsH 24576..33280 (2 x 16x136), BsL 33280..41984, aux 41984..42496
template<int MODE>
__global__ void __launch_bounds__(256, 2) gemm_mma(
    const float* __restrict__ A0, const float* __restrict__ A1,
    const bf16* __restrict__ Bh, const bf16* __restrict__ Bl,
    const float* __restrict__ bias, const float* __restrict__ dinv,
    float* __restrict__ C)
{
    extern __shared__ char sm[];
    constexpr int K  = MODE ? KH : KXL;
    constexpr int NC = K / 16;
    constexpr int LDC = MODE ? HX : KXL;

    bf16* AsH = (bf16*)(sm);
    bf16* AsL = (bf16*)(sm + 12288);
    bf16* BsH = (bf16*)(sm + 24576);
    bf16* BsL = (bf16*)(sm + 33280);
    float* aux = (float*)(sm + 41984);   // dinv_s (MODE0) or bias_s (MODE1)

    const int t = threadIdx.x, lane = t & 31, wid = t >> 5;
    const int wm = wid >> 1, wn = wid & 1;          // 4x2 warps, warp tile 32x64
    const size_t brow = (size_t)blockIdx.y * 128;
    const int bcol = blockIdx.x * 128;
    const int bidx = blockIdx.y;

    if (MODE == 0) { if (t < 128) aux[t] = dinv[brow + t]; }
    else           { if (t < 128) aux[t] = bias[bcol + t]; }

    const uint32_t aOffH = smem_u32(AsH) + ((wm * 32 + (lane & 15)) * 24 + (lane >> 4) * 8) * 2;
    const uint32_t aOffL = aOffH + 12288;
    const uint32_t bOffH = smem_u32(BsH) + ((lane & 15) * 136 + wn * 64 + ((lane >> 4) << 3)) * 2;
    const uint32_t bOffL = bOffH + 8704;

    float acc[2][8][4] = {};
    float4 pa0, pa1;
    uint4 pbh, pbl;
    const int arL = t >> 1, acg = (t & 1) * 8;      // A: row, 8-col group
    const int bk = t >> 4, bn8 = (t & 15) * 8;      // B: k-row, 8-col group

#define LOADG(k0) do {                                                        \
        int col = (k0) + acg;                                                 \
        const float* s;                                                       \
        if (MODE == 0)                                                        \
            s = (col < 256) ? A0 + (brow + arL) * 256 + col                   \
                            : A1 + (brow + arL) * 64 + (col - 256);           \
        else                                                                  \
            s = (col < 320) ? A0 + (brow + arL) * (size_t)KXL + col           \
                            : A1 + (size_t)bidx * 128 + (col - 320);          \
        pa0 = *(const float4*)s; pa1 = *(const float4*)(s + 4);               \
        pbh = *(const uint4*)(Bh + (size_t)((k0) + bk) * 256 + bcol + bn8);   \
        pbl = *(const uint4*)(Bl + (size_t)((k0) + bk) * 256 + bcol + bn8);   \
    } while (0)

#define STORES(buf) do {                                                      \
        uint4 ph, pl;                                                         \
        split2(pa0.x, pa0.y, ph.x, pl.x); split2(pa0.z, pa0.w, ph.y, pl.y);   \
        split2(pa1.x, pa1.y, ph.z, pl.z); split2(pa1.z, pa1.w, ph.w, pl.w);   \
        *(uint4*)(AsH + (buf) * 3072 + arL * 24 + acg) = ph;                  \
        *(uint4*)(AsL + (buf) * 3072 + arL * 24 + acg) = pl;                  \
        *(uint4*)(BsH + (buf) * 2176 + bk * 136 + bn8) = pbh;                 \
        *(uint4*)(BsL + (buf) * 2176 + bk * 136 + bn8) = pbl;                 \
    } while (0)

    LOADG(0);
    int buf = 0;
#pragma unroll 1
    for (int c = 0; c < NC; c++) {
        STORES(buf);
        if (c + 1 < NC) LOADG((c + 1) * 16);
        __syncthreads();
        uint32_t ah[2][4], al[2][4];
#pragma unroll
        for (int mt = 0; mt < 2; mt++) {
            LDSM_X4(ah[mt][0], ah[mt][1], ah[mt][2], ah[mt][3], aOffH + buf * 6144 + mt * 768);
            LDSM_X4(al[mt][0], al[mt][1], al[mt][2], al[mt][3], aOffL + buf * 6144 + mt * 768);
        }
#pragma unroll
        for (int np = 0; np < 4; np++) {
            uint32_t bh[4], bl[4];
            LDSM_X4T(bh[0], bh[1], bh[2], bh[3], bOffH + buf * 4352 + np * 32);
            LDSM_X4T(bl[0], bl[1], bl[2], bl[3], bOffL + buf * 4352 + np * 32);
#pragma unroll
            for (int mt = 0; mt < 2; mt++) {
                mma16816(acc[mt][np * 2],     ah[mt], bh[0], bh[1]);
                mma16816(acc[mt][np * 2 + 1], ah[mt], bh[2], bh[3]);
                mma16816(acc[mt][np * 2],     ah[mt], bl[0], bl[1]);
                mma16816(acc[mt][np * 2 + 1], ah[mt], bl[2], bl[3]);
                mma16816(acc[mt][np * 2],     al[mt], bh[0], bh[1]);
                mma16816(acc[mt][np * 2 + 1], al[mt], bh[2], bh[3]);
            }
        }
        buf ^= 1;
    }

    const int g = lane >> 2, q = (lane & 3) * 2;
#pragma unroll
    for (int mt = 0; mt < 2; mt++) {
        int r0loc = wm * 32 + mt * 16 + g;
#pragma unroll
        for (int nt = 0; nt < 8; nt++) {
            const float* a = acc[mt][nt];
            int lcol = wn * 64 + nt * 8 + q;
            int col = bcol + lcol;
            size_t r0 = brow + r0loc;
            if (MODE == 0) {
                float d0 = aux[r0loc], d1 = aux[r0loc + 8];
                *(float2*)&C[r0 * LDC + col]       = make_float2(a[0] * d0, a[1] * d0);
                *(float2*)&C[(r0 + 8) * LDC + col] = make_float2(a[2] * d1, a[3] * d1);
            } else {
                float b0 = aux[lcol], b1 = aux[lcol + 1];
                *(float2*)&C[r0 * LDC + col] =
                    make_float2(fmaxf(a[0] + b0, 0.f), fmaxf(a[1] + b1, 0.f));
                *(float2*)&C[(r0 + 8) * LDC + col] =
                    make_float2(fmaxf(a[2] + b0, 0.f), fmaxf(a[3] + b1, 0.f));
            }
        }
    }
#undef LOADG
#undef STORES
}

// ---------------- batched (A+I) MMA GEMM (R5, known-good 71us) ----------------
__global__ void __launch_bounds__(512) an_mma(
    const unsigned* __restrict__ mask, const float* __restrict__ dinv,
    const float* __restrict__ T,
    const float* __restrict__ bx, const float* __restrict__ bl,
    float* __restrict__ H)
{
    extern __shared__ char sm[];
    bf16* As  = (bf16*)(sm);
    bf16* BsH = (bf16*)(sm + 34816);
    bf16* BsL = (bf16*)(sm + 45568);
    float* bias_s = (float*)(sm + 56320);
    float* dinv_s = (float*)(sm + 56960);

    const int t = threadIdx.x, lane = t & 31, wid = t >> 5;
    const int wm = wid >> 1, wn = wid & 1;     // 8x2 warps; warp tile 16x80
    const int ct = blockIdx.x, b = blockIdx.y;
    const float* Tb = T + (size_t)b * 128 * KXL + ct * 160;

    {
        int i = t >> 2, jg = t & 3;
        unsigned m = mask[((size_t)b * 128 + i) * 4 + jg];
        uint32_t* dst = (uint32_t*)(As + i * 136 + jg * 32);
#pragma unroll
        for (int p = 0; p < 16; p++) {
            int j0 = jg * 32 + p * 2;
            uint32_t s0 = ((m >> (p * 2)) & 1u) + (j0 == i);
            uint32_t s1 = ((m >> (p * 2 + 1)) & 1u) + (j0 + 1 == i);
            uint32_t v0 = (s0 == 0) ? 0u : ((s0 == 1) ? 0x3F80u : 0x4000u);
            uint32_t v1 = (s1 == 0) ? 0u : ((s1 == 1) ? 0x3F80u : 0x4000u);
            dst[p] = v0 | (v1 << 16);
        }
    }
    if (t < 160) {
        int gcol = ct * 160 + t;
        bias_s[t] = (gcol < 256) ? bx[gcol] : bl[gcol - 256];
    }
    if (t >= 256 && t < 384) dinv_s[t - 256] = dinv[(size_t)b * 128 + (t - 256)];

    const uint32_t aOff = smem_u32(As) + ((wm * 16 + (lane & 15)) * 136 + (lane >> 4) * 8) * 2;
    const uint32_t bOffH = smem_u32(BsH) + ((lane & 15) * 168 + wn * 80 + ((lane >> 4) << 3)) * 2;
    const uint32_t bOffL = bOffH + 10752;

    float acc[10][4] = {};
    float4 pb0, pb1;
    const int k_0 = t / 40, n4_0 = t % 40;
    const int idx1 = t + 512;
    const int k_1 = idx1 / 40, n4_1 = idx1 % 40;

#define BLOAD(k0) do {                                                        \
        pb0 = *(const float4*)(Tb + (size_t)((k0) + k_0) * KXL + n4_0 * 4);   \
        if (idx1 < 640)                                                       \
            pb1 = *(const float4*)(Tb + (size_t)((k0) + k_1) * KXL + n4_1 * 4); \
    } while (0)

#define BSTORE(buf) do {                                                      \
        uint32_t h0, l0, h1, l1;                                              \
        split2(pb0.x, pb0.y, h0, l0); split2(pb0.z, pb0.w, h1, l1);           \
        *(uint2*)(BsH + (buf) * 2688 + k_0 * 168 + n4_0 * 4) = make_uint2(h0, h1); \
        *(uint2*)(BsL + (buf) * 2688 + k_0 * 168 + n4_0 * 4) = make_uint2(l0, l1); \
        if (idx1 < 640) {                                                     \
            split2(pb1.x, pb1.y, h0, l0); split2(pb1.z, pb1.w, h1, l1);       \
            *(uint2*)(BsH + (buf) * 2688 + k_1 * 168 + n4_1 * 4) = make_uint2(h0, h1); \
            *(uint2*)(BsL + (buf) * 2688 + k_1 * 168 + n4_1 * 4) = make_uint2(l0, l1); \
        }                                                                     \
    } while (0)

    BLOAD(0);
    int buf = 0;
#pragma unroll 1
    for (int c = 0; c < 8; c++) {
        BSTORE(buf);
        if (c + 1 < 8) BLOAD((c + 1) * 16);
        __syncthreads();
        uint32_t a[4];
        LDSM_X4(a[0], a[1], a[2], a[3], aOff + c * 32);
#pragma unroll
        for (int nt = 0; nt < 5; nt++) {
            uint32_t bh[4], blr[4];
            LDSM_X4T(bh[0], bh[1], bh[2], bh[3], bOffH + buf * 5376 + nt * 32);
            LDSM_X4T(blr[0], blr[1], blr[2], blr[3], bOffL + buf * 5376 + nt * 32);
            mma16816(acc[nt * 2],     a, bh[0], bh[1]);
            mma16816(acc[nt * 2 + 1], a, bh[2], bh[3]);
            mma16816(acc[nt * 2],     a, blr[0], blr[1]);
            mma16816(acc[nt * 2 + 1], a, blr[2], blr[3]);
        }
        buf ^= 1;
    }

    const int g = lane >> 2, q = (lane & 3) * 2;
    const int r0loc = wm * 16 + g;
    const float d0 = dinv_s[r0loc], d1 = dinv_s[r0loc + 8];
#pragma unroll
    for (int nt = 0; nt < 10; nt++) {
        const float* a = acc[nt];
        int lcol = wn * 80 + nt * 8 + q;
        int gcol = ct * 160 + lcol;
        float b0 = bias_s[lcol], b1 = bias_s[lcol + 1];
        size_t r0 = (size_t)b * 128 + r0loc;
        *(float2*)&H[r0 * KXL + gcol] =
            make_float2(fmaf(a[0], d0, b0), fmaf(a[1], d0, b1));
        *(float2*)&H[(r0 + 8) * KXL + gcol] =
            make_float2(fmaf(a[2], d1, b0), fmaf(a[3], d1, b1));
    }
#undef BLOAD
#undef BSTORE
}

// ---------------- LayerNorm over 256, block per row ----------------
__global__ void ln256_kernel(const float* __restrict__ Z, const float* __restrict__ g,
                             const float* __restrict__ be, float* __restrict__ out) {
    int row = blockIdx.x, t = threadIdx.x;
    size_t base = (size_t)row * HX;
    float v = Z[base + t];
    float s = warp_sum(v), s2 = warp_sum(v * v);
    __shared__ float rs[8], rs2[8];
    if ((t & 31) == 0) { rs[t >> 5] = s; rs2[t >> 5] = s2; }
    __syncthreads();
    float S = 0.f, S2 = 0.f;
#pragma unroll
    for (int i = 0; i < 8; i++) { S += rs[i]; S2 += rs2[i]; }
    float mean = S * (1.0f / HX);
    float var = S2 * (1.0f / HX) - mean * mean;
    float r = rsqrtf(var + 1e-5f);
    out[base + t] = (v - mean) * r * g[t] + be[t];
}

// ---------------- 64x64x64 SGEMM (label@Wl, dinv-scaled) ----------------
__global__ void sgemm64(const float* __restrict__ A, const float* __restrict__ B,
                        const float* __restrict__ dinv, float* __restrict__ C) {
    __shared__ float As[16][64];
    __shared__ float Bs[16][64];
    const int t = threadIdx.x;
    const size_t brow = (size_t)blockIdx.y * 64;
    const int tx = t & 15, ty = t >> 4;
    const int ar = t >> 2, ac = (t & 3) * 4;
    const int bkr = t >> 4, bc = (t & 15) * 4;
    float acc[4][4] = {};
    for (int k0 = 0; k0 < 64; k0 += 16) {
        float4 av = *(const float4*)(A + (brow + ar) * 64 + k0 + ac);
        As[ac + 0][ar] = av.x; As[ac + 1][ar] = av.y;
        As[ac + 2][ar] = av.z; As[ac + 3][ar] = av.w;
        *(float4*)&Bs[bkr][bc] = *(const float4*)(B + (size_t)(k0 + bkr) * 64 + bc);
        __syncthreads();
#pragma unroll
        for (int kk = 0; kk < 16; kk++) {
            float4 a0 = *(const float4*)&As[kk][ty * 4];
            float4 b0 = *(const float4*)&Bs[kk][tx * 4];
            float ra[4] = {a0.x, a0.y, a0.z, a0.w};
            float rb[4] = {b0.x, b0.y, b0.z, b0.w};
#pragma unroll
            for (int i = 0; i < 4; i++)
#pragma unroll
                for (int j = 0; j < 4; j++)
                    acc[i][j] = fmaf(ra[i], rb[j], acc[i][j]);
        }
        __syncthreads();
    }
#pragma unroll
    for (int i = 0; i < 4; i++) {
        size_t row = brow + ty * 4 + i;
        float d = dinv[row];
        float4 v;
        v.x = acc[i][0] * d; v.y = acc[i][1] * d;
        v.z = acc[i][2] * d; v.w = acc[i][3] * d;
        *(float4*)(C + row * KXL + 256 + tx * 4) = v;
    }
}

// ---------------- fused relu(la@W2+b2) + LN(64) ----------------
__global__ void label_out_kernel(const float* __restrict__ H, const float* __restrict__ W2,
                                 const float* __restrict__ b2, const float* __restrict__ g2,
                                 const float* __restrict__ be2, float* __restrict__ out) {
    __shared__ float W2s[64][64];
    __shared__ float las[8][64];
    const int t = threadIdx.x, w = t >> 5, l = t & 31;
#pragma unroll
    for (int i = 0; i < 4; i++) {
        int idx = t + i * 256;
        ((float4*)&W2s[0][0])[idx] = ((const float4*)W2)[idx];
    }
    size_t row = (size_t)blockIdx.x * 8 + w;
    const float* hrow = H + row * KXL + HX;
    las[w][l] = hrow[l];
    las[w][l + 32] = hrow[l + 32];
    __syncthreads();
    float acc0 = 0.f, acc1 = 0.f;
#pragma unroll
    for (int k = 0; k < 64; k++) {
        float v = las[w][k];
        acc0 = fmaf(v, W2s[k][l], acc0);
        acc1 = fmaf(v, W2s[k][l + 32], acc1);
    }
    acc0 = fmaxf(acc0 + b2[l], 0.f);
    acc1 = fmaxf(acc1 + b2[l + 32], 0.f);
    float mean = warp_sum(acc0 + acc1) * (1.0f / 64.0f);
    float sq = warp_sum(acc0 * acc0 + acc1 * acc1) * (1.0f / 64.0f);
    float r = rsqrtf(sq - mean * mean + 1e-5f);
    out[row * HL + l]      = (acc0 - mean) * r * g2[l] + be2[l];
    out[row * HL + l + 32] = (acc1 - mean) * r * g2[l + 32] + be2[l + 32];
}

// ---------------- launcher ----------------
extern "C" void kernel_launch(void* const* d_in, const int* in_sizes, int n_in,
                              void* d_out, int out_size) {
    const float* X     = (const float*)d_in[0];
    const int*   E     = (const int*)d_in[1];
    const float* y     = (const float*)d_in[2];
    const float* label = (const float*)d_in[3];
    const float* Wx  = (const float*)d_in[5];
    const float* bx  = (const float*)d_in[6];
    const float* Wl  = (const float*)d_in[7];
    const float* bl  = (const float*)d_in[8];
    const float* W1  = (const float*)d_in[9];
    const float* b1  = (const float*)d_in[10];
    const float* g1  = (const float*)d_in[11];
    const float* be1 = (const float*)d_in[12];
    const float* W2  = (const float*)d_in[13];
    const float* b2  = (const float*)d_in[14];
    const float* g2  = (const float*)d_in[15];
    const float* be2 = (const float*)d_in[16];
    float* out_X = (float*)d_out;
    float* out_L = out_X + (size_t)ROWS * HX;

    float *pdinv, *pT, *pH, *pZ;
    unsigned* pmask;
    bf16 *pWxh, *pWxl, *pW1h, *pW1l;
    cudaGetSymbolAddress((void**)&pdinv, g_dinv);
    cudaGetSymbolAddress((void**)&pmask, g_mask);
    cudaGetSymbolAddress((void**)&pT,    g_T);
    cudaGetSymbolAddress((void**)&pH,    g_H);
    cudaGetSymbolAddress((void**)&pZ,    g_Z);
    cudaGetSymbolAddress((void**)&pWxh,  g_Wxh);
    cudaGetSymbolAddress((void**)&pWxl,  g_Wxl);
    cudaGetSymbolAddress((void**)&pW1h,  g_W1h);
    cudaGetSymbolAddress((void**)&pW1l,  g_W1l);

    const int SMEM  = 42496;
    const int SMEMA = 57472;
    cudaFuncSetAttribute(gemm_mma<0>, cudaFuncAttributeMaxDynamicSharedMemorySize, SMEM);
    cudaFuncSetAttribute(gemm_mma<1>, cudaFuncAttributeMaxDynamicSharedMemorySize, SMEM);
    cudaFuncSetAttribute(an_mma,      cudaFuncAttributeMaxDynamicSharedMemorySize, SMEMA);

    dinv_mask_kernel<<<ROWS / 8, 256>>>(E, pdinv, pmask);
    wsplit_kernel<<<(320 * 256 + 255) / 256, 256>>>(Wx, 320 * 256, pWxh, pWxl);
    wsplit_kernel<<<(448 * 256 + 255) / 256, 256>>>(W1, 448 * 256, pW1h, pW1l);

    gemm_mma<0><<<dim3(2, 512), 256, SMEM>>>(X, label, pWxh, pWxl, nullptr, pdinv, pT);
    sgemm64<<<dim3(1, ROWS / 64), 256>>>(label, Wl, pdinv, pT);

    an_mma<<<dim3(2, BSZ), 512, SMEMA>>>(pmask, pdinv, pT, bx, bl, pH);

    gemm_mma<1><<<dim3(2, 512), 256, SMEM>>>(pH, y, pW1h, pW1l, b1, nullptr, pZ);
    ln256_kernel<<<ROWS, 256>>>(pZ, g1, be1, out_X);

    label_out_kernel<<<ROWS / 8, 256>>>(pH, W2, b2, g2, be2, out_L);
}

// round 8
// speedup vs baseline: 1.2555x; 1.1547x over previous
#include <cuda_runtime.h>
#include <cuda_bf16.h>
#include <cstdint>

#define BSZ 512
#define NN  128
#define HX  256
#define HL  64
#define HY  128
#define ROWS (BSZ*NN)          // 65536
#define KXL 320
#define KH  448

typedef __nv_bfloat16 bf16;

// ---------------- scratch ----------------
__device__ float    g_dinv[ROWS];
__device__ unsigned g_mask[(size_t)ROWS*4];
__device__ float    g_T [(size_t)ROWS*KXL];     // 84 MB (dinv-scaled T)
__device__ float    g_H [(size_t)ROWS*KXL];     // 84 MB
__device__ bf16     g_Wxh[320*256], g_Wxl[320*256];
__device__ bf16     g_W1h[448*256], g_W1l[448*256];

// ---------------- helpers ----------------
__device__ __forceinline__ uint32_t smem_u32(const void* p) {
    uint32_t a;
    asm("{ .reg .u64 t; cvta.to.shared.u64 t, %1; cvt.u32.u64 %0, t; }" : "=r"(a) : "l"(p));
    return a;
}
__device__ __forceinline__ float warp_sum(float v) {
#pragma unroll
    for (int o = 16; o; o >>= 1) v += __shfl_xor_sync(0xffffffffu, v, o);
    return v;
}
__device__ __forceinline__ void split2(float a, float b, uint32_t& hi, uint32_t& lo) {
    __nv_bfloat162 h = __floats2bfloat162_rn(a, b);
    float ra = a - __bfloat162float(h.x);
    float rb = b - __bfloat162float(h.y);
    __nv_bfloat162 l = __floats2bfloat162_rn(ra, rb);
    hi = *(uint32_t*)&h;
    lo = *(uint32_t*)&l;
}

#define LDSM_X4(R0,R1,R2,R3,ADDR) \
    asm volatile("ldmatrix.sync.aligned.m8n8.x4.shared.b16 {%0,%1,%2,%3}, [%4];" \
        : "=r"(R0), "=r"(R1), "=r"(R2), "=r"(R3) : "r"(ADDR))
#define LDSM_X4T(R0,R1,R2,R3,ADDR) \
    asm volatile("ldmatrix.sync.aligned.m8n8.x4.trans.shared.b16 {%0,%1,%2,%3}, [%4];" \
        : "=r"(R0), "=r"(R1), "=r"(R2), "=r"(R3) : "r"(ADDR))

__device__ __forceinline__ void mma16816(float* c, const uint32_t* a, uint32_t b0, uint32_t b1) {
    asm volatile("mma.sync.aligned.m16n8k16.row.col.f32.bf16.bf16.f32 "
        "{%0,%1,%2,%3}, {%4,%5,%6,%7}, {%8,%9}, {%0,%1,%2,%3};"
        : "+f"(c[0]), "+f"(c[1]), "+f"(c[2]), "+f"(c[3])
        : "r"(a[0]), "r"(a[1]), "r"(a[2]), "r"(a[3]), "r"(b0), "r"(b1));
}

// ---------------- prep: degree + adjacency bitmask ----------------
__global__ void dinv_mask_kernel(const int* __restrict__ E, float* __restrict__ dinv,
                                 unsigned* __restrict__ mask) {
    int t = threadIdx.x, w = t >> 5, l = t & 31;
    size_t row = (size_t)blockIdx.x * 8 + w;
    const int* er = E + row * 256 + 1;
    int cnt = 0;
#pragma unroll
    for (int c = 0; c < 4; c++) {
        unsigned b = __ballot_sync(0xffffffffu, er[(size_t)(c * 32 + l) * 2] != 0);
        if (l == 0) mask[row * 4 + c] = b;
        cnt += __popc(b);
    }
    if (l == 0) dinv[row] = rsqrtf((float)cnt + 1.0f);
}

// ---------------- prep: split weights into bf16 planes ----------------
__global__ void wsplit_kernel(const float* __restrict__ W, int total,
                              bf16* __restrict__ oh, bf16* __restrict__ ol) {
    int idx = blockIdx.x * 256 + threadIdx.x;
    if (idx >= total) return;
    float v = W[idx];
    bf16 h = __float2bfloat16(v);
    oh[idx] = h;
    ol[idx] = __float2bfloat16(v - __bfloat162float(h));
}

// ---------------- gemm0: 128x128 block, 256 threads, 2 CTAs/SM (R7, 93us) ----------
// T[:, bcol:bcol+128] = dinv * ([X|label] @ Wx)  (K=320, ldc 320)
__global__ void __launch_bounds__(256, 2) gemm0_mma(
    const float* __restrict__ A0, const float* __restrict__ A1,
    const bf16* __restrict__ Bh, const bf16* __restrict__ Bl,
    const float* __restrict__ dinv, float* __restrict__ C)
{
    extern __shared__ char sm[];
    bf16* AsH = (bf16*)(sm);
    bf16* AsL = (bf16*)(sm + 12288);
    bf16* BsH = (bf16*)(sm + 24576);
    bf16* BsL = (bf16*)(sm + 33280);
    float* aux = (float*)(sm + 41984);

    const int t = threadIdx.x, lane = t & 31, wid = t >> 5;
    const int wm = wid >> 1, wn = wid & 1;
    const size_t brow = (size_t)blockIdx.y * 128;
    const int bcol = blockIdx.x * 128;

    if (t < 128) aux[t] = dinv[brow + t];

    const uint32_t aOffH = smem_u32(AsH) + ((wm * 32 + (lane & 15)) * 24 + (lane >> 4) * 8) * 2;
    const uint32_t aOffL = aOffH + 12288;
    const uint32_t bOffH = smem_u32(BsH) + ((lane & 15) * 136 + wn * 64 + ((lane >> 4) << 3)) * 2;
    const uint32_t bOffL = bOffH + 8704;

    float acc[2][8][4] = {};
    float4 pa0, pa1;
    uint4 pbh, pbl;
    const int arL = t >> 1, acg = (t & 1) * 8;
    const int bk = t >> 4, bn8 = (t & 15) * 8;

#define LOADG0(k0) do {                                                       \
        int col = (k0) + acg;                                                 \
        const float* s = (col < 256) ? A0 + (brow + arL) * 256 + col          \
                                     : A1 + (brow + arL) * 64 + (col - 256);  \
        pa0 = *(const float4*)s; pa1 = *(const float4*)(s + 4);               \
        pbh = *(const uint4*)(Bh + (size_t)((k0) + bk) * 256 + bcol + bn8);   \
        pbl = *(const uint4*)(Bl + (size_t)((k0) + bk) * 256 + bcol + bn8);   \
    } while (0)

#define STORES0(buf) do {                                                     \
        uint4 ph, pl;                                                         \
        split2(pa0.x, pa0.y, ph.x, pl.x); split2(pa0.z, pa0.w, ph.y, pl.y);   \
        split2(pa1.x, pa1.y, ph.z, pl.z); split2(pa1.z, pa1.w, ph.w, pl.w);   \
        *(uint4*)(AsH + (buf) * 3072 + arL * 24 + acg) = ph;                  \
        *(uint4*)(AsL + (buf) * 3072 + arL * 24 + acg) = pl;                  \
        *(uint4*)(BsH + (buf) * 2176 + bk * 136 + bn8) = pbh;                 \
        *(uint4*)(BsL + (buf) * 2176 + bk * 136 + bn8) = pbl;                 \
    } while (0)

    LOADG0(0);
    int buf = 0;
#pragma unroll 1
    for (int c = 0; c < 20; c++) {
        STORES0(buf);
        if (c + 1 < 20) LOADG0((c + 1) * 16);
        __syncthreads();
        uint32_t ah[2][4], al[2][4];
#pragma unroll
        for (int mt = 0; mt < 2; mt++) {
            LDSM_X4(ah[mt][0], ah[mt][1], ah[mt][2], ah[mt][3], aOffH + buf * 6144 + mt * 768);
            LDSM_X4(al[mt][0], al[mt][1], al[mt][2], al[mt][3], aOffL + buf * 6144 + mt * 768);
        }
#pragma unroll
        for (int np = 0; np < 4; np++) {
            uint32_t bh[4], bl[4];
            LDSM_X4T(bh[0], bh[1], bh[2], bh[3], bOffH + buf * 4352 + np * 32);
            LDSM_X4T(bl[0], bl[1], bl[2], bl[3], bOffL + buf * 4352 + np * 32);
#pragma unroll
            for (int mt = 0; mt < 2; mt++) {
                mma16816(acc[mt][np * 2],     ah[mt], bh[0], bh[1]);
                mma16816(acc[mt][np * 2 + 1], ah[mt], bh[2], bh[3]);
                mma16816(acc[mt][np * 2],     ah[mt], bl[0], bl[1]);
                mma16816(acc[mt][np * 2 + 1], ah[mt], bl[2], bl[3]);
                mma16816(acc[mt][np * 2],     al[mt], bh[0], bh[1]);
                mma16816(acc[mt][np * 2 + 1], al[mt], bh[2], bh[3]);
            }
        }
        buf ^= 1;
    }

    const int g = lane >> 2, q = (lane & 3) * 2;
#pragma unroll
    for (int mt = 0; mt < 2; mt++) {
        int r0loc = wm * 32 + mt * 16 + g;
        float d0 = aux[r0loc], d1 = aux[r0loc + 8];
#pragma unroll
        for (int nt = 0; nt < 8; nt++) {
            const float* a = acc[mt][nt];
            int col = bcol + wn * 64 + nt * 8 + q;
            size_t r0 = brow + r0loc;
            *(float2*)&C[r0 * KXL + col]       = make_float2(a[0] * d0, a[1] * d0);
            *(float2*)&C[(r0 + 8) * KXL + col] = make_float2(a[2] * d1, a[3] * d1);
        }
    }
#undef LOADG0
#undef STORES0
}

// ---------------- gemm1 fused LN: 64x256 block, 256 threads, 2 CTAs/SM ----------------
// out_X[brow..brow+64, :] = LN(relu([H|y] @ W1 + b1))   (K=448)
// smem: AsH 0 (2x64x24), AsL 6144, BsH 12288 (2x16x264), BsL 29184,
//       bias 46080, gam 47104, bet 48128, rsum 49152, rsq 50176, mstd 51200 (end 51712)
__global__ void __launch_bounds__(256, 2) gemm1_ln(
    const float* __restrict__ Hm, const float* __restrict__ y,
    const bf16* __restrict__ Bh, const bf16* __restrict__ Bl,
    const float* __restrict__ bias, const float* __restrict__ gam,
    const float* __restrict__ bet, float* __restrict__ C)
{
    extern __shared__ char sm[];
    bf16* AsH = (bf16*)(sm);
    bf16* AsL = (bf16*)(sm + 6144);
    bf16* BsH = (bf16*)(sm + 12288);
    bf16* BsL = (bf16*)(sm + 29184);
    float* bias_s = (float*)(sm + 46080);
    float* gam_s  = (float*)(sm + 47104);
    float* bet_s  = (float*)(sm + 48128);
    float* rsum   = (float*)(sm + 49152);
    float* rsq    = (float*)(sm + 50176);
    float* mstd   = (float*)(sm + 51200);

    const int t = threadIdx.x, lane = t & 31, wid = t >> 5;
    const int wm = wid >> 2, wn = wid & 3;          // 2x4 warps, warp tile 32x64
    const size_t brow = (size_t)blockIdx.x * 64;

    if (t < 256) { bias_s[t] = bias[t]; gam_s[t] = gam[t]; bet_s[t] = bet[t]; }

    const uint32_t aOffH = smem_u32(AsH) + ((wm * 32 + (lane & 15)) * 24 + (lane >> 4) * 8) * 2;
    const uint32_t aOffL = aOffH + 6144;
    const uint32_t bOffH = smem_u32(BsH) + ((lane & 15) * 264 + wn * 64 + ((lane >> 4) << 3)) * 2;
    const uint32_t bOffL = bOffH + 16896;

    float acc[2][8][4] = {};
    float4 pa;
    uint4 pbh[2], pbl[2];
    const int arL = t >> 2, ac4 = (t & 3) * 4;      // A: 64 rows x 4-col groups
    const int bk = t >> 5, bn8 = (t & 31) * 8;      // B(idx t): k, col
    const size_t bidx = (brow + arL) >> 7;

#define LOADG1(k0) do {                                                       \
        int col = (k0) + ac4;                                                 \
        const float* s = (col < 320)                                          \
            ? Hm + (brow + arL) * (size_t)KXL + col                           \
            : y + bidx * 128 + (col - 320);                                   \
        pa = *(const float4*)s;                                               \
        _Pragma("unroll")                                                     \
        for (int j = 0; j < 2; j++) {                                         \
            int k = bk + j * 8;                                               \
            pbh[j] = *(const uint4*)(Bh + (size_t)((k0) + k) * 256 + bn8);    \
            pbl[j] = *(const uint4*)(Bl + (size_t)((k0) + k) * 256 + bn8);    \
        }                                                                     \
    } while (0)

#define STORES1(buf) do {                                                     \
        uint2 ph, pl;                                                         \
        split2(pa.x, pa.y, ph.x, pl.x); split2(pa.z, pa.w, ph.y, pl.y);       \
        *(uint2*)(AsH + (buf) * 1536 + arL * 24 + ac4) = ph;                  \
        *(uint2*)(AsL + (buf) * 1536 + arL * 24 + ac4) = pl;                  \
        _Pragma("unroll")                                                     \
        for (int j = 0; j < 2; j++) {                                         \
            int k = bk + j * 8;                                               \
            *(uint4*)(BsH + (buf) * 4224 + k * 264 + bn8) = pbh[j];           \
            *(uint4*)(BsL + (buf) * 4224 + k * 264 + bn8) = pbl[j];           \
        }                                                                     \
    } while (0)

    LOADG1(0);
    int buf = 0;
#pragma unroll 1
    for (int c = 0; c < 28; c++) {
        STORES1(buf);
        if (c + 1 < 28) LOADG1((c + 1) * 16);
        __syncthreads();
        uint32_t ah[2][4], al[2][4];
#pragma unroll
        for (int mt = 0; mt < 2; mt++) {
            LDSM_X4(ah[mt][0], ah[mt][1], ah[mt][2], ah[mt][3], aOffH + buf * 3072 + mt * 768);
            LDSM_X4(al[mt][0], al[mt][1], al[mt][2], al[mt][3], aOffL + buf * 3072 + mt * 768);
        }
#pragma unroll
        for (int np = 0; np < 4; np++) {
            uint32_t bh[4], bl[4];
            LDSM_X4T(bh[0], bh[1], bh[2], bh[3], bOffH + buf * 8448 + np * 32);
            LDSM_X4T(bl[0], bl[1], bl[2], bl[3], bOffL + buf * 8448 + np * 32);
#pragma unroll
            for (int mt = 0; mt < 2; mt++) {
                mma16816(acc[mt][np * 2],     ah[mt], bh[0], bh[1]);
                mma16816(acc[mt][np * 2 + 1], ah[mt], bh[2], bh[3]);
                mma16816(acc[mt][np * 2],     ah[mt], bl[0], bl[1]);
                mma16816(acc[mt][np * 2 + 1], ah[mt], bl[2], bl[3]);
                mma16816(acc[mt][np * 2],     al[mt], bh[0], bh[1]);
                mma16816(acc[mt][np * 2 + 1], al[mt], bh[2], bh[3]);
            }
        }
        buf ^= 1;
    }

    const int g = lane >> 2, q = (lane & 3) * 2;
    // partial row sums of relu(acc + bias)
#pragma unroll
    for (int mt = 0; mt < 2; mt++) {
#pragma unroll
        for (int hf = 0; hf < 2; hf++) {
            float s = 0.f, qq = 0.f;
#pragma unroll
            for (int nt = 0; nt < 8; nt++) {
                int col = wn * 64 + nt * 8 + q;
                float v0 = fmaxf(acc[mt][nt][hf * 2]     + bias_s[col],     0.f);
                float v1 = fmaxf(acc[mt][nt][hf * 2 + 1] + bias_s[col + 1], 0.f);
                s += v0 + v1; qq += v0 * v0 + v1 * v1;
            }
            s  += __shfl_xor_sync(0xffffffffu, s, 1);
            s  += __shfl_xor_sync(0xffffffffu, s, 2);
            qq += __shfl_xor_sync(0xffffffffu, qq, 1);
            qq += __shfl_xor_sync(0xffffffffu, qq, 2);
            if ((lane & 3) == 0) {
                int row = wm * 32 + mt * 16 + hf * 8 + g;
                rsum[row * 4 + wn] = s;
                rsq [row * 4 + wn] = qq;
            }
        }
    }
    __syncthreads();
    if (t < 64) {
        float S = rsum[t * 4] + rsum[t * 4 + 1] + rsum[t * 4 + 2] + rsum[t * 4 + 3];
        float Q = rsq [t * 4] + rsq [t * 4 + 1] + rsq [t * 4 + 2] + rsq [t * 4 + 3];
        float mean = S * (1.0f / 256.0f);
        float var  = Q * (1.0f / 256.0f) - mean * mean;
        mstd[t * 2]     = mean;
        mstd[t * 2 + 1] = rsqrtf(var + 1e-5f);
    }
    __syncthreads();
#pragma unroll
    for (int mt = 0; mt < 2; mt++)
#pragma unroll
        for (int nt = 0; nt < 8; nt++) {
            const float* a = acc[mt][nt];
            int col = wn * 64 + nt * 8 + q;
            float b0 = bias_s[col], b1 = bias_s[col + 1];
            float g0 = gam_s[col],  g1 = gam_s[col + 1];
            float e0 = bet_s[col],  e1 = bet_s[col + 1];
            int r0 = wm * 32 + mt * 16 + g;
            float m0 = mstd[r0 * 2], s0 = mstd[r0 * 2 + 1];
            float m1 = mstd[(r0 + 8) * 2], s1 = mstd[(r0 + 8) * 2 + 1];
            float v0 = fmaxf(a[0] + b0, 0.f), v1 = fmaxf(a[1] + b1, 0.f);
            float v2 = fmaxf(a[2] + b0, 0.f), v3 = fmaxf(a[3] + b1, 0.f);
            *(float2*)&C[(brow + r0) * (size_t)HX + col] =
                make_float2((v0 - m0) * s0 * g0 + e0, (v1 - m0) * s0 * g1 + e1);
            *(float2*)&C[(brow + r0 + 8) * (size_t)HX + col] =
                make_float2((v2 - m1) * s1 * g0 + e0, (v3 - m1) * s1 * g1 + e1);
        }
#undef LOADG1
#undef STORES1
}

// ---------------- batched (A+I) MMA GEMM: 128x80 block, 256 threads, 2 CTAs/SM ------
__global__ void __launch_bounds__(256, 2) an_mma(
    const unsigned* __restrict__ mask, const float* __restrict__ dinv,
    const float* __restrict__ T,
    const float* __restrict__ bx, const float* __restrict__ bl,
    float* __restrict__ H)
{
    __shared__ bf16 As[128 * 136];
    __shared__ bf16 BsH[2][16 * 88];
    __shared__ bf16 BsL[2][16 * 88];
    __shared__ float bias_s[80];
    __shared__ float dinv_s[128];

    const int t = threadIdx.x, lane = t & 31, wid = t >> 5;   // 8 warps, 16 rows each
    const int ct = blockIdx.x, b = blockIdx.y;
    const float* Tb = T + (size_t)b * 128 * KXL + ct * 80;

    // A01 = adj + I, exact bf16 {0,1,2}
#pragma unroll
    for (int j = 0; j < 2; j++) {
        int idx = t + j * 256;
        int i = idx >> 2, jg = idx & 3;
        unsigned m = mask[((size_t)b * 128 + i) * 4 + jg];
        uint32_t* dst = (uint32_t*)(As + i * 136 + jg * 32);
#pragma unroll
        for (int p = 0; p < 16; p++) {
            int j0 = jg * 32 + p * 2;
            uint32_t s0 = ((m >> (p * 2)) & 1u) + (j0 == i);
            uint32_t s1 = ((m >> (p * 2 + 1)) & 1u) + (j0 + 1 == i);
            uint32_t v0 = (s0 == 0) ? 0u : ((s0 == 1) ? 0x3F80u : 0x4000u);
            uint32_t v1 = (s1 == 0) ? 0u : ((s1 == 1) ? 0x3F80u : 0x4000u);
            dst[p] = v0 | (v1 << 16);
        }
    }
    if (t < 80) {
        int gcol = ct * 80 + t;
        bias_s[t] = (gcol < 256) ? bx[gcol] : bl[gcol - 256];
    }
    if (t >= 128 && t < 256) dinv_s[t - 128] = dinv[(size_t)b * 128 + (t - 128)];

    const uint32_t aOff = smem_u32(As) + ((wid * 16 + (lane & 15)) * 136 + (lane >> 4) * 8) * 2;
    const uint32_t bOffH = smem_u32(BsH) + ((lane & 15) * 88 + ((lane >> 4) << 3)) * 2;
    const uint32_t bOffL = smem_u32(BsL) + ((lane & 15) * 88 + ((lane >> 4) << 3)) * 2;

    float acc[10][4] = {};
    float4 pb0, pb1;
    const int k_0 = t / 20, n4_0 = t % 20;          // idx t: 16x20 float4 slots = 320
    const int idx1 = t + 256;
    const int k_1 = idx1 / 20, n4_1 = idx1 % 20;

#define BLOAD(k0) do {                                                        \
        if (t < 320)                                                          \
            pb0 = *(const float4*)(Tb + (size_t)((k0) + k_0) * KXL + n4_0 * 4); \
        if (idx1 < 320)                                                       \
            pb1 = *(const float4*)(Tb + (size_t)((k0) + k_1) * KXL + n4_1 * 4); \
    } while (0)

#define BSTORE(buf) do {                                                      \
        uint32_t h0, l0, h1, l1;                                              \
        if (t < 320) {                                                        \
            split2(pb0.x, pb0.y, h0, l0); split2(pb0.z, pb0.w, h1, l1);       \
            *(uint2*)(&BsH[buf][0] + k_0 * 88 + n4_0 * 4) = make_uint2(h0, h1); \
            *(uint2*)(&BsL[buf][0] + k_0 * 88 + n4_0 * 4) = make_uint2(l0, l1); \
        }                                                                     \
        if (idx1 < 320) {                                                     \
            split2(pb1.x, pb1.y, h0, l0); split2(pb1.z, pb1.w, h1, l1);       \
            *(uint2*)(&BsH[buf][0] + k_1 * 88 + n4_1 * 4) = make_uint2(h0, h1); \
            *(uint2*)(&BsL[buf][0] + k_1 * 88 + n4_1 * 4) = make_uint2(l0, l1); \
        }                                                                     \
    } while (0)

    BLOAD(0);
    int buf = 0;
#pragma unroll 1
    for (int c = 0; c < 8; c++) {
        BSTORE(buf);
        if (c + 1 < 8) BLOAD((c + 1) * 16);
        __syncthreads();
        uint32_t a[4];
        LDSM_X4(a[0], a[1], a[2], a[3], aOff + c * 32);
#pragma unroll
        for (int nt = 0; nt < 5; nt++) {
            uint32_t bh[4], blr[4];
            LDSM_X4T(bh[0], bh[1], bh[2], bh[3], bOffH + buf * 2816 + nt * 32);
            LDSM_X4T(blr[0], blr[1], blr[2], blr[3], bOffL + buf * 2816 + nt * 32);
            mma16816(acc[nt * 2],     a, bh[0], bh[1]);
            mma16816(acc[nt * 2 + 1], a, bh[2], bh[3]);
            mma16816(acc[nt * 2],     a, blr[0], blr[1]);
            mma16816(acc[nt * 2 + 1], a, blr[2], blr[3]);
        }
        buf ^= 1;
    }

    const int g = lane >> 2, q = (lane & 3) * 2;
    const int r0loc = wid * 16 + g;
    const float d0 = dinv_s[r0loc], d1 = dinv_s[r0loc + 8];
#pragma unroll
    for (int nt = 0; nt < 10; nt++) {
        const float* a = acc[nt];
        int lcol = nt * 8 + q;
        int gcol = ct * 80 + lcol;
        float b0 = bias_s[lcol], b1 = bias_s[lcol + 1];
        size_t r0 = (size_t)b * 128 + r0loc;
        *(float2*)&H[r0 * KXL + gcol] =
            make_float2(fmaf(a[0], d0, b0), fmaf(a[1], d0, b1));
        *(float2*)&H[(r0 + 8) * KXL + gcol] =
            make_float2(fmaf(a[2], d1, b0), fmaf(a[3], d1, b1));
    }
#undef BLOAD
#undef BSTORE
}

// ---------------- 64x64x64 SGEMM (label@Wl, dinv-scaled) ----------------
__global__ void sgemm64(const float* __restrict__ A, const float* __restrict__ B,
                        const float* __restrict__ dinv, float* __restrict__ C) {
    __shared__ float As[16][64];
    __shared__ float Bs[16][64];
    const int t = threadIdx.x;
    const size_t brow = (size_t)blockIdx.y * 64;
    const int tx = t & 15, ty = t >> 4;
    const int ar = t >> 2, ac = (t & 3) * 4;
    const int bkr = t >> 4, bc = (t & 15) * 4;
    float acc[4][4] = {};
    for (int k0 = 0; k0 < 64; k0 += 16) {
        float4 av = *(const float4*)(A + (brow + ar) * 64 + k0 + ac);
        As[ac + 0][ar] = av.x; As[ac + 1][ar] = av.y;
        As[ac + 2][ar] = av.z; As[ac + 3][ar] = av.w;
        *(float4*)&Bs[bkr][bc] = *(const float4*)(B + (size_t)(k0 + bkr) * 64 + bc);
        __syncthreads();
#pragma unroll
        for (int kk = 0; kk < 16; kk++) {
            float4 a0 = *(const float4*)&As[kk][ty * 4];
            float4 b0 = *(const float4*)&Bs[kk][tx * 4];
            float ra[4] = {a0.x, a0.y, a0.z, a0.w};
            float rb[4] = {b0.x, b0.y, b0.z, b0.w};
#pragma unroll
            for (int i = 0; i < 4; i++)
#pragma unroll
                for (int j = 0; j < 4; j++)
                    acc[i][j] = fmaf(ra[i], rb[j], acc[i][j]);
        }
        __syncthreads();
    }
#pragma unroll
    for (int i = 0; i < 4; i++) {
        size_t row = brow + ty * 4 + i;
        float d = dinv[row];
        float4 v;
        v.x = acc[i][0] * d; v.y = acc[i][1] * d;
        v.z = acc[i][2] * d; v.w = acc[i][3] * d;
        *(float4*)(C + row * KXL + 256 + tx * 4) = v;
    }
}

// ---------------- fused relu(la@W2+b2) + LN(64) ----------------
__global__ void label_out_kernel(const float* __restrict__ H, const float* __restrict__ W2,
                                 const float* __restrict__ b2, const float* __restrict__ g2,
                                 const float* __restrict__ be2, float* __restrict__ out) {
    __shared__ float W2s[64][64];
    __shared__ float las[8][64];
    const int t = threadIdx.x, w = t >> 5, l = t & 31;
#pragma unroll
    for (int i = 0; i < 4; i++) {
        int idx = t + i * 256;
        ((float4*)&W2s[0][0])[idx] = ((const float4*)W2)[idx];
    }
    size_t row = (size_t)blockIdx.x * 8 + w;
    const float* hrow = H + row * KXL + HX;
    las[w][l] = hrow[l];
    las[w][l + 32] = hrow[l + 32];
    __syncthreads();
    float acc0 = 0.f, acc1 = 0.f;
#pragma unroll
    for (int k = 0; k < 64; k++) {
        float v = las[w][k];
        acc0 = fmaf(v, W2s[k][l], acc0);
        acc1 = fmaf(v, W2s[k][l + 32], acc1);
    }
    acc0 = fmaxf(acc0 + b2[l], 0.f);
    acc1 = fmaxf(acc1 + b2[l + 32], 0.f);
    float mean = warp_sum(acc0 + acc1) * (1.0f / 64.0f);
    float sq = warp_sum(acc0 * acc0 + acc1 * acc1) * (1.0f / 64.0f);
    float r = rsqrtf(sq - mean * mean + 1e-5f);
    out[row * HL + l]      = (acc0 - mean) * r * g2[l] + be2[l];
    out[row * HL + l + 32] = (acc1 - mean) * r * g2[l + 32] + be2[l + 32];
}

// ---------------- launcher ----------------
extern "C" void kernel_launch(void* const* d_in, const int* in_sizes, int n_in,
                              void* d_out, int out_size) {
    const float* X     = (const float*)d_in[0];
    const int*   E     = (const int*)d_in[1];
    const float* y     = (const float*)d_in[2];
    const float* label = (const float*)d_in[3];
    const float* Wx  = (const float*)d_in[5];
    const float* bx  = (const float*)d_in[6];
    const float* Wl  = (const float*)d_in[7];
    const float* bl  = (const float*)d_in[8];
    const float* W1  = (const float*)d_in[9];
    const float* b1  = (const float*)d_in[10];
    const float* g1  = (const float*)d_in[11];
    const float* be1 = (const float*)d_in[12];
    const float* W2  = (const float*)d_in[13];
    const float* b2  = (const float*)d_in[14];
    const float* g2  = (const float*)d_in[15];
    const float* be2 = (const float*)d_in[16];
    float* out_X = (float*)d_out;
    float* out_L = out_X + (size_t)ROWS * HX;

    float *pdinv, *pT, *pH;
    unsigned* pmask;
    bf16 *pWxh, *pWxl, *pW1h, *pW1l;
    cudaGetSymbolAddress((void**)&pdinv, g_dinv);
    cudaGetSymbolAddress((void**)&pmask, g_mask);
    cudaGetSymbolAddress((void**)&pT,    g_T);
    cudaGetSymbolAddress((void**)&pH,    g_H);
    cudaGetSymbolAddress((void**)&pWxh,  g_Wxh);
    cudaGetSymbolAddress((void**)&pWxl,  g_Wxl);
    cudaGetSymbolAddress((void**)&pW1h,  g_W1h);
    cudaGetSymbolAddress((void**)&pW1l,  g_W1l);

    const int SMEM0 = 42496;
    const int SMEM1 = 51712;
    cudaFuncSetAttribute(gemm0_mma, cudaFuncAttributeMaxDynamicSharedMemorySize, SMEM0);
    cudaFuncSetAttribute(gemm1_ln,  cudaFuncAttributeMaxDynamicSharedMemorySize, SMEM1);

    dinv_mask_kernel<<<ROWS / 8, 256>>>(E, pdinv, pmask);
    wsplit_kernel<<<(320 * 256 + 255) / 256, 256>>>(Wx, 320 * 256, pWxh, pWxl);
    wsplit_kernel<<<(448 * 256 + 255) / 256, 256>>>(W1, 448 * 256, pW1h, pW1l);

    gemm0_mma<<<dim3(2, 512), 256, SMEM0>>>(X, label, pWxh, pWxl, pdinv, pT);
    sgemm64<<<dim3(1, ROWS / 64), 256>>>(label, Wl, pdinv, pT);

    an_mma<<<dim3(4, BSZ), 256>>>(pmask, pdinv, pT, bx, bl, pH);

    gemm1_ln<<<1024, 256, SMEM1>>>(pH, y, pW1h, pW1l, b1, g1, be1, out_X);

    label_out_kernel<<<ROWS / 8, 256>>>(pH, W2, b2, g2, be2, out_L);
}